// round 4
// baseline (speedup 1.0000x reference)
#include <cuda_runtime.h>
#include <math.h>

#define T_LEN 256
#define HID   2048
#define NHEAD 16
#define DHEAD 128
#define KD    2048
#define CHUNK 16
#define NSLOT (T_LEN / CHUNK)

// ---------------- scratch ----------------
__device__ float g_Q0[T_LEN * KD];
__device__ float g_K0[T_LEN * KD];
__device__ float g_V0[T_LEN * KD];
__device__ float g_qn[T_LEN * KD];
__device__ float g_kn[T_LEN * KD];
__device__ float g_beta[T_LEN * NHEAD];
__device__ float g_decay[T_LEN * NHEAD];
__device__ float g_lamb[KD];
__device__ float g_on[T_LEN * KD];
__device__ float g_hkk_ck[(size_t)NSLOT * NHEAD * DHEAD * DHEAD];  // 16 MB
__device__ float g_hkv_ck[(size_t)NSLOT * NHEAD * DHEAD * DHEAD];  // 16 MB

// ---------------- f32x2 helpers ----------------
typedef unsigned long long u64;
__device__ __forceinline__ u64 splat2(float a) {
    u64 d; unsigned u = __float_as_uint(a);
    asm("mov.b64 %0, {%1, %1};" : "=l"(d) : "r"(u));
    return d;
}
__device__ __forceinline__ void ffma2(u64& d, u64 a, u64 b) {
    asm("fma.rn.f32x2 %0, %1, %2, %0;" : "+l"(d) : "l"(a), "l"(b));
}
__device__ __forceinline__ void mul2(u64& d, u64 a) {
    asm("mul.rn.f32x2 %0, %0, %1;" : "+l"(d) : "l"(a));
}
__device__ __forceinline__ float2 unpk(u64 v) {
    unsigned lo, hi;
    asm("mov.b64 {%0, %1}, %2;" : "=r"(lo), "=r"(hi) : "l"(v));
    return make_float2(__uint_as_float(lo), __uint_as_float(hi));
}

// ---------------- GEMM 128x64 tile (qkv) ----------------
// NOTE: A-tile pad must keep the row stride a multiple of 16B for float4 STS.
__device__ __forceinline__ void gemm_tile128(const float* __restrict__ X,
                                             const float* __restrict__ W,
                                             float* __restrict__ C, int N,
                                             int m0, int n0) {
    __shared__ __align__(16) float As[128][36];   // stride 144B = 9*16, aligned
    __shared__ __align__(16) float Bs[32][64];
    const int tid = threadIdx.x;
    const int tn4 = (tid & 15) * 4;
    const int tm8 = (tid >> 4) * 8;
    const int arow = tid >> 1;
    const int akoff = (tid & 1) * 16;
    const int brow = tid >> 3;
    const int bcol = (tid & 7) * 8;

    u64 acc[8][2];
#pragma unroll
    for (int i = 0; i < 8; i++) { acc[i][0] = 0ull; acc[i][1] = 0ull; }

    for (int k0 = 0; k0 < HID; k0 += 32) {
        const float* xp = &X[(m0 + arow) * HID + k0 + akoff];
#pragma unroll
        for (int q = 0; q < 4; q++)
            *(float4*)&As[arow][akoff + q * 4] = *(const float4*)&xp[q * 4];
        const float* wp = &W[(k0 + brow) * N + n0 + bcol];
        *(float4*)&Bs[brow][bcol]     = *(const float4*)&wp[0];
        *(float4*)&Bs[brow][bcol + 4] = *(const float4*)&wp[4];
        __syncthreads();
#pragma unroll
        for (int kk = 0; kk < 32; kk++) {
            ulonglong2 bv = *(const ulonglong2*)&Bs[kk][tn4];
#pragma unroll
            for (int i = 0; i < 8; i++) {
                u64 s = splat2(As[tm8 + i][kk]);
                ffma2(acc[i][0], s, bv.x);
                ffma2(acc[i][1], s, bv.y);
            }
        }
        __syncthreads();
    }
#pragma unroll
    for (int i = 0; i < 8; i++) {
        float2 lo = unpk(acc[i][0]);
        float2 hi = unpk(acc[i][1]);
        *(float4*)&C[(m0 + tm8 + i) * N + n0 + tn4] = make_float4(lo.x, lo.y, hi.x, hi.y);
    }
}

// ---------------- GEMM 64x64 tile (out) ----------------
__device__ __forceinline__ void gemm_tile64(const float* __restrict__ X,
                                            const float* __restrict__ W,
                                            float* __restrict__ C, int N,
                                            int m0, int n0) {
    __shared__ __align__(16) float As[64][36];
    __shared__ __align__(16) float Bs[32][64];
    const int tid = threadIdx.x;
    const int tn4 = (tid & 15) * 4;
    const int tm4 = (tid >> 4) * 4;
    const int lrow = tid >> 2;
    const int lk   = (tid & 3) * 8;
    const int bkk  = tid >> 3;
    const int bn8  = (tid & 7) * 8;

    u64 acc[4][2];
#pragma unroll
    for (int i = 0; i < 4; i++) { acc[i][0] = 0ull; acc[i][1] = 0ull; }

    for (int k0 = 0; k0 < HID; k0 += 32) {
        float4 xa = *(const float4*)&X[(m0 + lrow) * HID + k0 + lk];
        float4 xb = *(const float4*)&X[(m0 + lrow) * HID + k0 + lk + 4];
        *(float4*)&As[lrow][lk]     = xa;
        *(float4*)&As[lrow][lk + 4] = xb;
        float4 wa = *(const float4*)&W[(k0 + bkk) * N + n0 + bn8];
        float4 wb = *(const float4*)&W[(k0 + bkk) * N + n0 + bn8 + 4];
        *(float4*)&Bs[bkk][bn8]     = wa;
        *(float4*)&Bs[bkk][bn8 + 4] = wb;
        __syncthreads();
#pragma unroll
        for (int kk = 0; kk < 32; kk++) {
            ulonglong2 bv = *(const ulonglong2*)&Bs[kk][tn4];
            u64 s0 = splat2(As[tm4 + 0][kk]);
            u64 s1 = splat2(As[tm4 + 1][kk]);
            u64 s2 = splat2(As[tm4 + 2][kk]);
            u64 s3 = splat2(As[tm4 + 3][kk]);
            ffma2(acc[0][0], s0, bv.x); ffma2(acc[0][1], s0, bv.y);
            ffma2(acc[1][0], s1, bv.x); ffma2(acc[1][1], s1, bv.y);
            ffma2(acc[2][0], s2, bv.x); ffma2(acc[2][1], s2, bv.y);
            ffma2(acc[3][0], s3, bv.x); ffma2(acc[3][1], s3, bv.y);
        }
        __syncthreads();
    }
#pragma unroll
    for (int i = 0; i < 4; i++) {
        float2 lo = unpk(acc[i][0]);
        float2 hi = unpk(acc[i][1]);
        *(float4*)&C[(m0 + tm4 + i) * N + n0 + tn4] = make_float4(lo.x, lo.y, hi.x, hi.y);
    }
}

__global__ void __launch_bounds__(256) qkv_kernel(const float* __restrict__ x,
                                                  const float* __restrict__ Wq,
                                                  const float* __restrict__ Wk,
                                                  const float* __restrict__ Wv) {
    const int gx = blockIdx.x;
    const int mat = gx % 3;
    const int n0 = (gx / 3) * 64;
    const int m0 = blockIdx.y * 128;
    const float* W = (mat == 0) ? Wq : (mat == 1) ? Wk : Wv;
    float* C = (mat == 0) ? g_Q0 : (mat == 1) ? g_K0 : g_V0;
    gemm_tile128(x, W, C, KD, m0, n0);
}

__global__ void __launch_bounds__(256) out_kernel(const float* __restrict__ Wo,
                                                  float* __restrict__ out) {
    gemm_tile64(g_on, Wo, out, HID, blockIdx.y * 64, blockIdx.x * 64);
}

// ---------------- beta / decay mini-GEMM ----------------
__global__ void __launch_bounds__(256) bg_kernel(const float* __restrict__ x,
                                                 const float* __restrict__ Wa,
                                                 const float* __restrict__ ba,
                                                 const float* __restrict__ Wb,
                                                 const float* __restrict__ bb) {
    __shared__ float Xs[32][17];
    __shared__ float Ws[32][32];
    const int tid = threadIdx.x;
    const int m0 = blockIdx.x * 16;
    const int n = tid & 31;
    const int mg = tid >> 5;
    const int lxm = tid >> 4;
    const int lxk = (tid & 15) * 2;

    float acc0 = 0.f, acc1 = 0.f;
    for (int k0 = 0; k0 < HID; k0 += 32) {
        float2 xv = *(const float2*)&x[(m0 + lxm) * HID + k0 + lxk];
        Xs[lxk][lxm] = xv.x;
        Xs[lxk + 1][lxm] = xv.y;
        const int i4 = tid * 4;
        const int wk = i4 >> 5, wn = i4 & 31;
#pragma unroll
        for (int j = 0; j < 4; j++) {
            int nn = wn + j;
            Ws[wk][nn] = (nn < 16) ? Wa[(k0 + wk) * NHEAD + nn]
                                   : Wb[(k0 + wk) * NHEAD + nn - 16];
        }
        __syncthreads();
#pragma unroll
        for (int kk = 0; kk < 32; kk++) {
            float w = Ws[kk][n];
            acc0 += Xs[kk][mg * 2] * w;
            acc1 += Xs[kk][mg * 2 + 1] * w;
        }
        __syncthreads();
    }
    const int row0 = m0 + mg * 2;
    if (n < 16) {
        float z0 = acc0 + ba[n], z1 = acc1 + ba[n];
        g_decay[row0 * NHEAD + n] = 1.f / (1.f + expf(-z0));
        g_decay[(row0 + 1) * NHEAD + n] = 1.f / (1.f + expf(-z1));
    } else {
        int c = n - 16;
        float z0 = acc0 + bb[c], z1 = acc1 + bb[c];
        g_beta[row0 * NHEAD + c] = 1.f / (1.f + expf(-z0));
        g_beta[(row0 + 1) * NHEAD + c] = 1.f / (1.f + expf(-z1));
    }
}

// ---------------- lambda ----------------
__global__ void lamb_kernel(const float* __restrict__ lp) {
    int i = blockIdx.x * 256 + threadIdx.x;
    if (i < KD) {
        float v = lp[i];
        float sp = (v > 20.f) ? v : log1pf(expf(v));
        g_lamb[i] = sp + 0.25f;
    }
}

// ---------------- conv(4)+silu+l2norm ----------------
__device__ __forceinline__ void conv_silu_l2(const float* __restrict__ src,
                                             const float* __restrict__ cw,
                                             float* __restrict__ dst,
                                             int t, int tid) {
    const int c0 = tid * 8;
    float wv[8][4];
#pragma unroll
    for (int e = 0; e < 8; e++) {
        float4 f = *(const float4*)&cw[(c0 + e) * 4];
        wv[e][0] = f.x; wv[e][1] = f.y; wv[e][2] = f.z; wv[e][3] = f.w;
    }
    float y[8];
#pragma unroll
    for (int e = 0; e < 8; e++) y[e] = 0.f;
#pragma unroll
    for (int i = 0; i < 4; i++) {
        int ts = t + i - 3;
        if (ts >= 0) {
            float4 xa = *(const float4*)&src[ts * HID + c0];
            float4 xb = *(const float4*)&src[ts * HID + c0 + 4];
            float xv[8] = {xa.x, xa.y, xa.z, xa.w, xb.x, xb.y, xb.z, xb.w};
#pragma unroll
            for (int e = 0; e < 8; e++) y[e] += xv[e] * wv[e][i];
        }
    }
#pragma unroll
    for (int e = 0; e < 8; e++) {
        float s = 1.f / (1.f + expf(-y[e]));
        y[e] *= s;
    }
    float ss = 0.f;
#pragma unroll
    for (int e = 0; e < 8; e++) ss += y[e] * y[e];
#pragma unroll
    for (int off = 1; off <= 8; off <<= 1) ss += __shfl_xor_sync(0xffffffffu, ss, off);
    float sc = rsqrtf(ss + 1e-6f);
    float4 o0 = make_float4(y[0] * sc, y[1] * sc, y[2] * sc, y[3] * sc);
    float4 o1 = make_float4(y[4] * sc, y[5] * sc, y[6] * sc, y[7] * sc);
    *(float4*)&dst[t * HID + c0] = o0;
    *(float4*)&dst[t * HID + c0 + 4] = o1;
}

__global__ void prep_kernel(const float* __restrict__ cwq, const float* __restrict__ cwk) {
    const int t = blockIdx.x;
    const int tid = threadIdx.x;
    conv_silu_l2(g_Q0, cwq, g_qn, t, tid);
    conv_silu_l2(g_K0, cwk, g_kn, t, tid);
}

// ---------------- state scan: only chunk-boundary checkpoints ----------------
__global__ void scan_kernel() {
    const int h = blockIdx.y;
    const int i0 = blockIdx.x * 8;
    const int tid = threadIdx.x;
    __shared__ float ds[T_LEN], bs[T_LEN];
    __shared__ __align__(16) float ks[2][DHEAD], vs[2][DHEAD];
    ds[tid] = g_decay[tid * NHEAD + h];
    bs[tid] = g_beta[tid * NHEAD + h];
    if (tid < 32)
        *(float4*)&ks[0][tid * 4] = *(const float4*)&g_kn[h * DHEAD + tid * 4];
    else if (tid < 64) {
        int l = tid - 32;
        *(float4*)&vs[0][l * 4] = *(const float4*)&g_V0[h * DHEAD + l * 4];
    }
    const int row = i0 + (tid >> 5);
    const int j0 = (tid & 31) * 4;
    float kk0 = 0, kk1 = 0, kk2 = 0, kk3 = 0;
    float kv0 = 0, kv1 = 0, kv2 = 0, kv3 = 0;
    for (int t = 0; t < T_LEN; t++) {
        __syncthreads();
        const int cb = t & 1, nb = (t + 1) & 1;
        if (t + 1 < T_LEN) {
            if (tid < 32)
                *(float4*)&ks[nb][tid * 4] =
                    *(const float4*)&g_kn[(t + 1) * HID + h * DHEAD + tid * 4];
            else if (tid < 64) {
                int l = tid - 32;
                *(float4*)&vs[nb][l * 4] =
                    *(const float4*)&g_V0[(t + 1) * HID + h * DHEAD + l * 4];
            }
        }
        const float d = ds[t], b = bs[t];
        const float kr = ks[cb][row];
        float4 kj = *(const float4*)&ks[cb][j0];
        float4 vj = *(const float4*)&vs[cb][j0];
        const float bk = b * kr;
        kk0 = kk0 * d + bk * kj.x; kk1 = kk1 * d + bk * kj.y;
        kk2 = kk2 * d + bk * kj.z; kk3 = kk3 * d + bk * kj.w;
        kv0 = kv0 * d + bk * vj.x; kv1 = kv1 * d + bk * vj.y;
        kv2 = kv2 * d + bk * vj.z; kv3 = kv3 * d + bk * vj.w;
        if (((t + 1) & (CHUNK - 1)) == 0) {
            const int slot = t >> 4;
            size_t base = (((size_t)slot * NHEAD + h) << 14) + (size_t)row * DHEAD + j0;
            *(float4*)&g_hkk_ck[base] = make_float4(kk0, kk1, kk2, kk3);
            *(float4*)&g_hkv_ck[base] = make_float4(kv0, kv1, kv2, kv3);
        }
    }
}

// ---------------- block reduce (parity-buffered) ----------------
__device__ __forceinline__ float blockReduce128(float v, int pb) {
    __shared__ float red[2][4];
#pragma unroll
    for (int off = 16; off > 0; off >>= 1) v += __shfl_xor_sync(0xffffffffu, v, off);
    const int w = threadIdx.x >> 5;
    if ((threadIdx.x & 31) == 0) red[pb][w] = v;
    __syncthreads();
    return red[pb][0] + red[pb][1] + red[pb][2] + red[pb][3];
}

// ---------------- CG solve (+ in-register A reconstruct) + output + rmsnorm ----------------
__global__ void __launch_bounds__(128, 3) solve_kernel(const float* __restrict__ onw) {
    const int h = blockIdx.x;
    const int t = blockIdx.y;
    const int r = threadIdx.x;
    const int cs = t & ~(CHUNK - 1);
    const int jend = t - cs;
    const int slot = (t >> 4) - 1;

    __shared__ __align__(16) float ks[CHUNK][DHEAD];
    __shared__ __align__(16) float vs[CHUNK][DHEAD];
    __shared__ __align__(16) float ps[DHEAD];
    __shared__ float dsh[CHUNK], bsh[CHUNK], Pp[CHUNK], cf[CHUNK], gsh[CHUNK];

    {
        const int row = r >> 3;
        const int c0 = (r & 7) * 16;
        const float* kp = &g_kn[(cs + row) * HID + h * DHEAD + c0];
        const float* vp = &g_V0[(cs + row) * HID + h * DHEAD + c0];
#pragma unroll
        for (int q = 0; q < 4; q++) {
            *(float4*)&ks[row][c0 + q * 4] = *(const float4*)&kp[q * 4];
            *(float4*)&vs[row][c0 + q * 4] = *(const float4*)&vp[q * 4];
        }
        if (r < CHUNK) {
            dsh[r] = g_decay[(cs + r) * NHEAD + h];
            bsh[r] = g_beta[(cs + r) * NHEAD + h];
        }
    }
    __syncthreads();
    if (r == 0) {
        float run = 1.f;
#pragma unroll
        for (int s = 0; s < CHUNK; s++) {
            run *= dsh[s];
            Pp[s] = run;
            cf[s] = bsh[s] / run;
        }
    }
    __syncthreads();
    const float Pt = Pp[jend];

    // build A row r in registers
    ulonglong2 A2[32];
    if (slot >= 0) {
        const float* base = g_hkk_ck + (((size_t)slot * NHEAD + h) << 14) + (size_t)r * DHEAD;
#pragma unroll
        for (int i = 0; i < 32; i++) A2[i] = *(const ulonglong2*)&base[i * 4];
    } else {
#pragma unroll
        for (int i = 0; i < 32; i++) { A2[i].x = 0ull; A2[i].y = 0ull; }
    }
    for (int s = 0; s <= jend; s++) {
        u64 w = splat2(cf[s] * ks[s][r]);
        const u64* kkp = (const u64*)&ks[s][0];
#pragma unroll
        for (int i = 0; i < 32; i++) {
            ffma2(A2[i].x, w, kkp[2 * i]);
            ffma2(A2[i].y, w, kkp[2 * i + 1]);
        }
    }
    {
        u64 pt2 = splat2(Pt);
#pragma unroll
        for (int i = 0; i < 32; i++) { mul2(A2[i].x, pt2); mul2(A2[i].y, pt2); }
    }

    const float lam = g_lamb[h * DHEAD + r];
    const float b = g_qn[t * HID + h * DHEAD + r];

    float xx = 0.f, rr = b, p = b;
    ps[r] = b;
    int par = 0;
    float rs = blockReduce128(b * b, par); par ^= 1;

    for (int it = 0; it < 30; it++) {
        u64 aA = 0ull, aB = 0ull, aC = 0ull, aD = 0ull;
#pragma unroll
        for (int i = 0; i < 32; i += 2) {
            ulonglong2 p0 = *(const ulonglong2*)&ps[i * 4];
            ulonglong2 p1 = *(const ulonglong2*)&ps[i * 4 + 4];
            ffma2(aA, A2[i].x, p0.x);     ffma2(aB, A2[i].y, p0.y);
            ffma2(aC, A2[i + 1].x, p1.x); ffma2(aD, A2[i + 1].y, p1.y);
        }
        float2 fa = unpk(aA), fb = unpk(aB), fc = unpk(aC), fd = unpk(aD);
        float ap = ((fa.x + fa.y) + (fb.x + fb.y)) + ((fc.x + fc.y) + (fd.x + fd.y)) + lam * p;
        float pap = blockReduce128(p * ap, par); par ^= 1;
        float alpha = rs / (pap + 1e-12f);
        xx += alpha * p;
        rr -= alpha * ap;
        float rsn = blockReduce128(rr * rr, par); par ^= 1;
        float bet = rsn / (rs + 1e-12f);
        p = rr + bet * p;
        rs = rsn;
        ps[r] = p;
        __syncthreads();
    }

    // ---- output: o = Pt * (x^T hkv_base) + sum_s cf[s]*Pt * (k_s . x) * v_s ----
    ps[r] = xx;
    __syncthreads();

    // dots g_s = k_s . x (8 threads per s)
    {
        const int sIdx = r >> 3;
        const int part = r & 7;
        float pg = 0.f;
        const int e0 = part * 16;
#pragma unroll
        for (int e = 0; e < 16; e++) pg += ks[sIdx][e0 + e] * ps[e0 + e];
#pragma unroll
        for (int off = 1; off <= 4; off <<= 1) pg += __shfl_xor_sync(0xffffffffu, pg, off);
        if (part == 0)
            gsh[sIdx] = (sIdx <= jend) ? pg * cf[sIdx] * Pt : 0.f;
    }
    __syncthreads();

    float o = 0.f;
    if (slot >= 0) {
        const float* kvb = g_hkv_ck + (((size_t)slot * NHEAD + h) << 14) + r;
        float o0 = 0, o1 = 0, o2 = 0, o3 = 0;
#pragma unroll
        for (int k2 = 0; k2 < DHEAD; k2 += 4) {
            o0 += ps[k2]     * kvb[(size_t)k2 * DHEAD];
            o1 += ps[k2 + 1] * kvb[(size_t)(k2 + 1) * DHEAD];
            o2 += ps[k2 + 2] * kvb[(size_t)(k2 + 2) * DHEAD];
            o3 += ps[k2 + 3] * kvb[(size_t)(k2 + 3) * DHEAD];
        }
        o = Pt * ((o0 + o1) + (o2 + o3));
    }
#pragma unroll
    for (int s = 0; s < CHUNK; s++) o += gsh[s] * vs[s][r];

    float ms = blockReduce128(o * o, par) * (1.0f / 128.0f);
    float sc = rsqrtf(ms + 1e-5f);
    g_on[t * HID + h * DHEAD + r] = o * sc * onw[r];
}

// ---------------- launch ----------------
extern "C" void kernel_launch(void* const* d_in, const int* in_sizes, int n_in,
                              void* d_out, int out_size) {
    const float* x    = (const float*)d_in[0];
    const float* Wq   = (const float*)d_in[1];
    const float* Wk   = (const float*)d_in[2];
    const float* Wv   = (const float*)d_in[3];
    const float* Wa   = (const float*)d_in[4];
    const float* ba   = (const float*)d_in[5];
    const float* Wb   = (const float*)d_in[6];
    const float* bb   = (const float*)d_in[7];
    const float* cwq  = (const float*)d_in[8];
    const float* cwk  = (const float*)d_in[9];
    const float* lp   = (const float*)d_in[10];
    const float* onw  = (const float*)d_in[11];
    const float* Wo   = (const float*)d_in[12];
    float* out = (float*)d_out;

    qkv_kernel<<<dim3(96, 2), 256>>>(x, Wq, Wk, Wv);
    bg_kernel<<<16, 256>>>(x, Wa, ba, Wb, bb);
    lamb_kernel<<<KD / 256, 256>>>(lp);
    prep_kernel<<<T_LEN, 256>>>(cwq, cwk);
    scan_kernel<<<dim3(16, NHEAD), 256>>>();
    solve_kernel<<<dim3(NHEAD, T_LEN), 128>>>(onw);
    out_kernel<<<dim3(HID / 64, T_LEN / 64), 256>>>(Wo, out);
}